// round 6
// baseline (speedup 1.0000x reference)
#include <cuda_runtime.h>
#include <stdint.h>
#include <math.h>

#define D_MODEL     1024
#define EXPERT_DIM  2048
#define NUM_EXPERTS 16
#define SEQ_LEN     2048
#define BATCH       2
#define NTOK        (SEQ_LEN*BATCH)      // 4096 tokens
#define NASSIGN     (NTOK*2)             // 8192 (token, k) assignments

// ---- scratch (static __device__: no allocations allowed) ----
__device__ float g_H[(size_t)NASSIGN * EXPERT_DIM];    // 64 MB (stored tf32-exact)
__device__ float g_Y[(size_t)NASSIGN * D_MODEL];       // 32 MB
__device__ float g_Xc[(size_t)NTOK * D_MODEL];         // 16 MB tf32-exact x
__device__ float g_W1c[(size_t)NUM_EXPERTS * D_MODEL * EXPERT_DIM];   // 128 MB
__device__ float g_W2c[(size_t)NUM_EXPERTS * EXPERT_DIM * D_MODEL];   // 128 MB
__device__ int   g_cnt[NUM_EXPERTS];
__device__ int   g_list[NUM_EXPERTS * NTOK];
__device__ float g_rw[NASSIGN];

__device__ __forceinline__ uint32_t f2tf32(float f) {
    uint32_t r;
    asm("cvt.rna.tf32.f32 %0, %1;" : "=r"(r) : "f"(f));
    return r;
}

__global__ void zero_cnt_kernel() {
    if (threadIdx.x < NUM_EXPERTS) g_cnt[threadIdx.x] = 0;
}

// ---- tf32-round a buffer (float4) ----
__global__ void cvt_kernel(const float* __restrict__ in, float* __restrict__ out, int n4) {
    int i = blockIdx.x * blockDim.x + threadIdx.x;
    if (i >= n4) return;
    float4 v = ((const float4*)in)[i];
    float4 o;
    o.x = __uint_as_float(f2tf32(v.x));
    o.y = __uint_as_float(f2tf32(v.y));
    o.z = __uint_as_float(f2tf32(v.z));
    o.w = __uint_as_float(f2tf32(v.w));
    ((float4*)out)[i] = o;
}

// ---- gating: one warp per token ----
__global__ void gate_kernel(const float* __restrict__ x,
                            const float* __restrict__ Wg,
                            const float* __restrict__ bg,
                            const float* __restrict__ bias) {
    int gwarp = (blockIdx.x * blockDim.x + threadIdx.x) >> 5;
    int lane  = threadIdx.x & 31;
    if (gwarp >= NTOK) return;
    const float* xr = x + (size_t)gwarp * D_MODEL;

    float xv[32];
    #pragma unroll
    for (int j = 0; j < 32; j++) xv[j] = xr[lane + 32 * j];

    float logits[NUM_EXPERTS];
    #pragma unroll
    for (int e = 0; e < NUM_EXPERTS; e++) {
        float s = 0.f;
        #pragma unroll
        for (int j = 0; j < 32; j++)
            s += xv[j] * Wg[(size_t)(lane + 32 * j) * NUM_EXPERTS + e];
        #pragma unroll
        for (int o = 16; o; o >>= 1) s += __shfl_xor_sync(0xffffffffu, s, o);
        logits[e] = s + bg[e] + bias[e];
    }

    if (lane == 0) {
        int e0 = 0; float v0 = logits[0];
        #pragma unroll
        for (int e = 1; e < NUM_EXPERTS; e++)
            if (logits[e] > v0) { v0 = logits[e]; e0 = e; }
        int e1 = -1; float v1 = -1e30f;
        #pragma unroll
        for (int e = 0; e < NUM_EXPERTS; e++)
            if (e != e0 && logits[e] > v1) { v1 = logits[e]; e1 = e; }

        float ew1 = __expf(v1 - v0);
        float inv = 1.f / (1.f + ew1);
        g_rw[gwarp * 2 + 0] = inv;
        g_rw[gwarp * 2 + 1] = ew1 * inv;
        int p0 = atomicAdd(&g_cnt[e0], 1);
        g_list[e0 * NTOK + p0] = gwarp * 2 + 0;
        int p1 = atomicAdd(&g_cnt[e1], 1);
        g_list[e1 * NTOK + p1] = gwarp * 2 + 1;
    }
}

// ================= mma + cp.async helpers =================
__device__ __forceinline__ void mma_tf32(float* d, const uint32_t* a, const uint32_t* b) {
    asm volatile(
        "mma.sync.aligned.m16n8k8.row.col.f32.tf32.tf32.f32 "
        "{%0,%1,%2,%3}, {%4,%5,%6,%7}, {%8,%9}, {%0,%1,%2,%3};\n"
        : "+f"(d[0]), "+f"(d[1]), "+f"(d[2]), "+f"(d[3])
        : "r"(a[0]), "r"(a[1]), "r"(a[2]), "r"(a[3]), "r"(b[0]), "r"(b[1]));
}
__device__ __forceinline__ void cpa16(uint32_t dst, const void* src) {
    asm volatile("cp.async.cg.shared.global [%0], [%1], 16;" :: "r"(dst), "l"(src));
}
#define CPA_COMMIT() asm volatile("cp.async.commit_group;" ::: "memory")
#define CPA_WAIT2()  asm volatile("cp.async.wait_group 2;" ::: "memory")

// smem layout (4-stage pipeline, k16 per stage, block tile 128m x 256n):
//   s_entry[128]            @ 0       (512 B)
//   A stages: 4 x 10240 B   @ 512     (A[m][k]: 128 rows, stride 20 floats)
//   B stages: 4 x 16896 B   @ 41472   (B[k][n]: 16 rows, stride 264 floats)
#define SM_A      512
#define SM_ASTG   10240
#define SM_B      41472
#define SM_BSTG   16896
#define SM_TOTAL  109056
#define ASTR      20
#define BSTR      264

template<int K, int N, bool FC1>
__global__ __launch_bounds__(256, 1)
void expert_mma(const float* __restrict__ Wbase,
                const float* __restrict__ BiasBase) {
    extern __shared__ char smem[];
    const int e   = blockIdx.z;
    const int cnt = g_cnt[e];
    const int m0  = blockIdx.y * 128;
    if (m0 >= cnt) return;
    const int n0  = blockIdx.x * 256;

    const float* W  = Wbase    + (size_t)e * K * N;
    const float* bv = BiasBase + (size_t)e * N;

    int* s_entry = (int*)smem;
    const uint32_t sbase = (uint32_t)__cvta_generic_to_shared(smem);

    const int tid = threadIdx.x;
    if (tid < 128) {
        int idx = m0 + tid;
        s_entry[tid] = (idx < cnt) ? g_list[e * NTOK + idx] : -1;
    }
    __syncthreads();

    // ---- producer mappings ----
    // A: 2 threads per row: row = tid>>1, 16B chunk at (tid&1)*8 floats
    const int arow_i = tid >> 1;
    const float* a_src;
    {
        int en = s_entry[arow_i];
        const float* base = FC1 ? g_Xc : g_H;
        size_t stride     = FC1 ? D_MODEL : EXPERT_DIM;
        size_t row        = (en >= 0) ? (size_t)(FC1 ? (en >> 1) : en) : 0;
        a_src = base + row * stride + (tid & 1) * 8;
    }
    const uint32_t a_dst0 = sbase + SM_A + arow_i * (ASTR * 4) + (tid & 1) * 32;
    // B: 16 threads per k-row: kr = tid>>4, 16 floats (4 chunks) per thread
    const int bkr = tid >> 4;
    const int bnf = (tid & 15) * 16;   // float offset within row
    const float* b_src = W + (size_t)bkr * N + n0 + bnf;
    const uint32_t b_dst0 = sbase + SM_B + (bkr * BSTR + bnf) * 4;

    auto produce = [&](int c, int s) {
        int k0 = c * 16;
        uint32_t ao = (uint32_t)(s * SM_ASTG);
        uint32_t bo = (uint32_t)(s * SM_BSTG);
        cpa16(a_dst0 + ao,      a_src + k0);
        cpa16(a_dst0 + ao + 16, a_src + k0 + 4);
        const float* bs = b_src + (size_t)k0 * N;
        #pragma unroll
        for (int j = 0; j < 4; j++)
            cpa16(b_dst0 + bo + j * 16, bs + j * 4);
    };

    // ---- consumer mappings: 8 warps = 2m x 4n, warp tile 64x64 ----
    const int lane = tid & 31;
    const int wid  = tid >> 5;
    const int m0w  = (wid & 1) * 64;
    const int n0w  = (wid >> 1) * 64;
    const int qr   = lane >> 2;
    const int qc   = lane & 3;

    float acc[4][8][4];
    #pragma unroll
    for (int mi = 0; mi < 4; mi++)
        #pragma unroll
        for (int ni = 0; ni < 8; ni++)
            #pragma unroll
            for (int j = 0; j < 4; j++) acc[mi][ni][j] = 0.f;

    const int nst = K / 16;

    produce(0, 0); CPA_COMMIT();
    produce(1, 1); CPA_COMMIT();
    produce(2, 2); CPA_COMMIT();

    for (int c = 0; c < nst; c++) {
        CPA_WAIT2();
        __syncthreads();
        if (c + 3 < nst) produce(c + 3, (c + 3) & 3);
        CPA_COMMIT();

        const uint32_t* Ab = (const uint32_t*)(smem + SM_A + (c & 3) * SM_ASTG);
        const uint32_t* Bb = (const uint32_t*)(smem + SM_B + (c & 3) * SM_BSTG);

        #pragma unroll
        for (int kk = 0; kk < 2; kk++) {
            const int kbase = kk * 8 + qc;
            uint32_t afrag[4][4];
            #pragma unroll
            for (int mi = 0; mi < 4; mi++) {
                int r = m0w + mi * 16 + qr;
                afrag[mi][0] = Ab[r * ASTR + kbase];
                afrag[mi][1] = Ab[(r + 8) * ASTR + kbase];
                afrag[mi][2] = Ab[r * ASTR + kbase + 4];
                afrag[mi][3] = Ab[(r + 8) * ASTR + kbase + 4];
            }
            uint32_t bfrag[8][2];
            #pragma unroll
            for (int ni = 0; ni < 8; ni++) {
                int nb = n0w + ni * 8 + qr;
                bfrag[ni][0] = Bb[kbase * BSTR + nb];
                bfrag[ni][1] = Bb[(kbase + 4) * BSTR + nb];
            }
            #pragma unroll
            for (int mi = 0; mi < 4; mi++)
                #pragma unroll
                for (int ni = 0; ni < 8; ni++)
                    mma_tf32(acc[mi][ni], afrag[mi], bfrag[ni]);
        }
    }

    // ---- epilogue ----
    #pragma unroll
    for (int mi = 0; mi < 4; mi++) {
        int r0 = m0w + mi * 16 + qr;
        int r1 = r0 + 8;
        int e0 = s_entry[r0];
        int e1 = s_entry[r1];
        #pragma unroll
        for (int ni = 0; ni < 8; ni++) {
            int ncol = n0 + n0w + ni * 8 + qc * 2;
            float bx = bv[ncol], by = bv[ncol + 1];
            if (FC1) {
                if (e0 >= 0) {
                    float* p = g_H + (size_t)e0 * EXPERT_DIM + ncol;
                    float v0 = acc[mi][ni][0] + bx;
                    float v1 = acc[mi][ni][1] + by;
                    v0 = v0 > 0.f ? v0 : 0.f;
                    v1 = v1 > 0.f ? v1 : 0.f;
                    *(float2*)p = make_float2(__uint_as_float(f2tf32(v0)),
                                              __uint_as_float(f2tf32(v1)));
                }
                if (e1 >= 0) {
                    float* p = g_H + (size_t)e1 * EXPERT_DIM + ncol;
                    float v0 = acc[mi][ni][2] + bx;
                    float v1 = acc[mi][ni][3] + by;
                    v0 = v0 > 0.f ? v0 : 0.f;
                    v1 = v1 > 0.f ? v1 : 0.f;
                    *(float2*)p = make_float2(__uint_as_float(f2tf32(v0)),
                                              __uint_as_float(f2tf32(v1)));
                }
            } else {
                if (e0 >= 0) {
                    float w = g_rw[e0];
                    float* p = g_Y + (size_t)e0 * D_MODEL + ncol;
                    *(float2*)p = make_float2(w * (acc[mi][ni][0] + bx),
                                              w * (acc[mi][ni][1] + by));
                }
                if (e1 >= 0) {
                    float w = g_rw[e1];
                    float* p = g_Y + (size_t)e1 * D_MODEL + ncol;
                    *(float2*)p = make_float2(w * (acc[mi][ni][2] + bx),
                                              w * (acc[mi][ni][3] + by));
                }
            }
        }
    }
}

// ---- combine: out[t] = Y[t, slot0] + Y[t, slot1] ----
__global__ void combine_kernel(float* __restrict__ out) {
    int idx = blockIdx.x * blockDim.x + threadIdx.x;
    if (idx >= NTOK * (D_MODEL / 4)) return;
    int t = idx / (D_MODEL / 4);
    int c = idx % (D_MODEL / 4);
    const float4* Y4 = (const float4*)g_Y;
    float4 a = Y4[(size_t)(2 * t + 0) * (D_MODEL / 4) + c];
    float4 b = Y4[(size_t)(2 * t + 1) * (D_MODEL / 4) + c];
    ((float4*)out)[idx] = make_float4(a.x + b.x, a.y + b.y, a.z + b.z, a.w + b.w);
}

extern "C" void kernel_launch(void* const* d_in, const int* in_sizes, int n_in,
                              void* d_out, int out_size) {
    (void)in_sizes; (void)n_in; (void)out_size;
    const float* x    = (const float*)d_in[0];
    const float* Wg   = (const float*)d_in[1];
    const float* bg   = (const float*)d_in[2];
    const float* bias = (const float*)d_in[3];
    const float* W1   = (const float*)d_in[4];
    const float* b1   = (const float*)d_in[5];
    const float* W2   = (const float*)d_in[6];
    const float* b2   = (const float*)d_in[7];
    float* out = (float*)d_out;

    static int attr_done = 0;
    if (!attr_done) {
        cudaFuncSetAttribute(expert_mma<D_MODEL, EXPERT_DIM, true>,
                             cudaFuncAttributeMaxDynamicSharedMemorySize, SM_TOTAL);
        cudaFuncSetAttribute(expert_mma<EXPERT_DIM, D_MODEL, false>,
                             cudaFuncAttributeMaxDynamicSharedMemorySize, SM_TOTAL);
        attr_done = 1;
    }

    zero_cnt_kernel<<<1, 32>>>();
    gate_kernel<<<NTOK / 8, 256>>>(x, Wg, bg, bias);

    {
        float* xc;  cudaGetSymbolAddress((void**)&xc,  g_Xc);
        float* w1c; cudaGetSymbolAddress((void**)&w1c, g_W1c);
        float* w2c; cudaGetSymbolAddress((void**)&w2c, g_W2c);
        int n4x = NTOK * D_MODEL / 4;
        int n4w = NUM_EXPERTS * D_MODEL * EXPERT_DIM / 4;
        cvt_kernel<<<(n4x + 255) / 256, 256>>>(x,  xc,  n4x);
        cvt_kernel<<<(n4w + 255) / 256, 256>>>(W1, w1c, n4w);
        cvt_kernel<<<(n4w + 255) / 256, 256>>>(W2, w2c, n4w);
    }

    float* w1c; cudaGetSymbolAddress((void**)&w1c, g_W1c);
    float* w2c; cudaGetSymbolAddress((void**)&w2c, g_W2c);

    expert_mma<D_MODEL, EXPERT_DIM, true >
        <<<dim3(EXPERT_DIM / 256, NTOK / 128, NUM_EXPERTS), 256, SM_TOTAL>>>(w1c, b1);
    expert_mma<EXPERT_DIM, D_MODEL, false>
        <<<dim3(D_MODEL / 256,  NTOK / 128, NUM_EXPERTS), 256, SM_TOTAL>>>(w2c, b2);
    combine_kernel<<<(NTOK * (D_MODEL / 4) + 255) / 256, 256>>>(out);
}

// round 7
// speedup vs baseline: 1.8842x; 1.8842x over previous
#include <cuda_runtime.h>
#include <cuda_fp16.h>
#include <stdint.h>
#include <math.h>

#define D_MODEL     1024
#define EXPERT_DIM  2048
#define NUM_EXPERTS 16
#define SEQ_LEN     2048
#define BATCH       2
#define NTOK        (SEQ_LEN*BATCH)      // 4096 tokens
#define NASSIGN     (NTOK*2)             // 8192 (token, k) assignments

// ---- scratch (static __device__: no allocations allowed) ----
__device__ __half g_Xh[(size_t)NTOK * D_MODEL];                        // 8 MB
__device__ __half g_Hh[(size_t)NASSIGN * EXPERT_DIM];                  // 32 MB
__device__ __half g_W1h[(size_t)NUM_EXPERTS * D_MODEL * EXPERT_DIM];   // 64 MB
__device__ __half g_W2h[(size_t)NUM_EXPERTS * EXPERT_DIM * D_MODEL];   // 64 MB
__device__ int   g_cnt[NUM_EXPERTS];
__device__ int   g_list[NUM_EXPERTS * NTOK];
__device__ float g_rw[NASSIGN];

__global__ void zero_cnt_kernel() {
    if (threadIdx.x < NUM_EXPERTS) g_cnt[threadIdx.x] = 0;
}

__global__ void zero_out_kernel(float4* __restrict__ out, int n4) {
    int i = blockIdx.x * blockDim.x + threadIdx.x;
    if (i < n4) out[i] = make_float4(0.f, 0.f, 0.f, 0.f);
}

// ---- fp32 -> fp16 (RN), 8 elems/thread ----
__global__ void cvt_h_kernel(const float* __restrict__ in, __half* __restrict__ out, int n8) {
    int i = blockIdx.x * blockDim.x + threadIdx.x;
    if (i >= n8) return;
    const float4* in4 = (const float4*)in;
    float4 a = in4[2 * i], b = in4[2 * i + 1];
    __half2 h[4];
    h[0] = __floats2half2_rn(a.x, a.y);
    h[1] = __floats2half2_rn(a.z, a.w);
    h[2] = __floats2half2_rn(b.x, b.y);
    h[3] = __floats2half2_rn(b.z, b.w);
    *(uint4*)(out + 8 * (size_t)i) = *(uint4*)h;
}

// ---- gating: one warp per token (fp32, raw x) ----
__global__ void gate_kernel(const float* __restrict__ x,
                            const float* __restrict__ Wg,
                            const float* __restrict__ bg,
                            const float* __restrict__ bias) {
    int gwarp = (blockIdx.x * blockDim.x + threadIdx.x) >> 5;
    int lane  = threadIdx.x & 31;
    if (gwarp >= NTOK) return;
    const float* xr = x + (size_t)gwarp * D_MODEL;

    float xv[32];
    #pragma unroll
    for (int j = 0; j < 32; j++) xv[j] = xr[lane + 32 * j];

    float logits[NUM_EXPERTS];
    #pragma unroll
    for (int e = 0; e < NUM_EXPERTS; e++) {
        float s = 0.f;
        #pragma unroll
        for (int j = 0; j < 32; j++)
            s += xv[j] * Wg[(size_t)(lane + 32 * j) * NUM_EXPERTS + e];
        #pragma unroll
        for (int o = 16; o; o >>= 1) s += __shfl_xor_sync(0xffffffffu, s, o);
        logits[e] = s + bg[e] + bias[e];
    }

    if (lane == 0) {
        int e0 = 0; float v0 = logits[0];
        #pragma unroll
        for (int e = 1; e < NUM_EXPERTS; e++)
            if (logits[e] > v0) { v0 = logits[e]; e0 = e; }
        int e1 = -1; float v1 = -1e30f;
        #pragma unroll
        for (int e = 0; e < NUM_EXPERTS; e++)
            if (e != e0 && logits[e] > v1) { v1 = logits[e]; e1 = e; }

        float ew1 = __expf(v1 - v0);
        float inv = 1.f / (1.f + ew1);
        g_rw[gwarp * 2 + 0] = inv;
        g_rw[gwarp * 2 + 1] = ew1 * inv;
        int p0 = atomicAdd(&g_cnt[e0], 1);
        g_list[e0 * NTOK + p0] = gwarp * 2 + 0;
        int p1 = atomicAdd(&g_cnt[e1], 1);
        g_list[e1 * NTOK + p1] = gwarp * 2 + 1;
    }
}

// ================= mma / ldmatrix / cp.async helpers =================
__device__ __forceinline__ void mma_f16(float* d, const uint32_t* a, const uint32_t* b) {
    asm volatile(
        "mma.sync.aligned.m16n8k16.row.col.f32.f16.f16.f32 "
        "{%0,%1,%2,%3}, {%4,%5,%6,%7}, {%8,%9}, {%0,%1,%2,%3};\n"
        : "+f"(d[0]), "+f"(d[1]), "+f"(d[2]), "+f"(d[3])
        : "r"(a[0]), "r"(a[1]), "r"(a[2]), "r"(a[3]), "r"(b[0]), "r"(b[1]));
}
__device__ __forceinline__ void ldsm4(uint32_t* r, uint32_t a) {
    asm volatile("ldmatrix.sync.aligned.m8n8.x4.shared.b16 {%0,%1,%2,%3}, [%4];"
        : "=r"(r[0]), "=r"(r[1]), "=r"(r[2]), "=r"(r[3]) : "r"(a));
}
__device__ __forceinline__ void ldsm4t(uint32_t* r, uint32_t a) {
    asm volatile("ldmatrix.sync.aligned.m8n8.x4.trans.shared.b16 {%0,%1,%2,%3}, [%4];"
        : "=r"(r[0]), "=r"(r[1]), "=r"(r[2]), "=r"(r[3]) : "r"(a));
}
__device__ __forceinline__ void cpa16(uint32_t dst, const void* src) {
    asm volatile("cp.async.cg.shared.global [%0], [%1], 16;" :: "r"(dst), "l"(src));
}
#define CPA_COMMIT() asm volatile("cp.async.commit_group;" ::: "memory")
#define CPA_WAIT2()  asm volatile("cp.async.wait_group 2;" ::: "memory")

// smem layout (4-stage, k16/stage, block tile 128m x 256n, fp16 operands):
//   s_entry[128]           @ 0
//   A stages: 4 x 6144 B   @ 512    (A[m][k]: 128 rows x 16 half, stride 48 B)
//   B stages: 4 x 8448 B   @ 25088  (B[k][n]: 16 rows x 256 half, stride 528 B)
#define ASTRB     48
#define BSTRB     528
#define SM_A      512
#define SM_ASTG   (128 * ASTRB)            // 6144
#define SM_B      (SM_A + 4 * SM_ASTG)     // 25088
#define SM_BSTG   (16 * BSTRB)             // 8448
#define SM_TOTAL  (SM_B + 4 * SM_BSTG)     // 58880

template<int K, int N, bool FC1>
__global__ __launch_bounds__(256, 1)
void expert_mma(const __half* __restrict__ Wbase,
                const float* __restrict__ BiasBase,
                float* __restrict__ out) {
    extern __shared__ char smem[];
    const int e   = blockIdx.z;
    const int cnt = g_cnt[e];
    const int m0  = blockIdx.y * 128;
    if (m0 >= cnt) return;
    const int n0  = blockIdx.x * 256;

    const __half* W  = Wbase    + (size_t)e * K * N;
    const float*  bv = BiasBase + (size_t)e * N;

    int* s_entry = (int*)smem;
    const uint32_t sbase = (uint32_t)__cvta_generic_to_shared(smem);

    const int tid = threadIdx.x;
    if (tid < 128) {
        int idx = m0 + tid;
        s_entry[tid] = (idx < cnt) ? g_list[e * NTOK + idx] : -1;
    }
    __syncthreads();

    // ---- producer mappings ----
    // A: 2 threads/row, each one 16B chunk (8 halfs) of the k16 slice
    const int arow_i = tid >> 1;
    const __half* a_src;
    {
        int en = s_entry[arow_i];
        const __half* base = FC1 ? g_Xh : g_Hh;
        size_t stride      = FC1 ? D_MODEL : EXPERT_DIM;
        size_t row         = (en >= 0) ? (size_t)(FC1 ? (en >> 1) : en) : 0;
        a_src = base + row * stride + (tid & 1) * 8;
    }
    const uint32_t a_dst0 = sbase + SM_A + arow_i * ASTRB + (tid & 1) * 16;
    // B: 16 threads per k-row, each 32B (two 16B chunks)
    const int bkr = tid >> 4;
    const int bnh = (tid & 15) * 16;    // half offset within row
    const __half* b_src = W + (size_t)bkr * N + n0 + bnh;
    const uint32_t b_dst0 = sbase + SM_B + bkr * BSTRB + (tid & 15) * 32;

    auto produce = [&](int c, int s) {
        int k0 = c * 16;
        cpa16(a_dst0 + s * SM_ASTG, a_src + k0);
        const __half* bs = b_src + (size_t)k0 * N;
        uint32_t bo = b_dst0 + s * SM_BSTG;
        cpa16(bo,      bs);
        cpa16(bo + 16, bs + 8);
    };

    // ---- consumer mappings: 8 warps = 2m x 4n, warp tile 64x64 ----
    const int lane = tid & 31;
    const int wid  = tid >> 5;
    const int m0w  = (wid & 1) * 64;
    const int n0w  = (wid >> 1) * 64;
    const int qr   = lane >> 2;
    const int qc   = lane & 3;
    const int l16  = lane & 15;
    const int lhi  = lane >> 4;

    float acc[4][8][4];
    #pragma unroll
    for (int mi = 0; mi < 4; mi++)
        #pragma unroll
        for (int ni = 0; ni < 8; ni++)
            #pragma unroll
            for (int j = 0; j < 4; j++) acc[mi][ni][j] = 0.f;

    const int nst = K / 16;

    produce(0, 0); CPA_COMMIT();
    produce(1, 1); CPA_COMMIT();
    produce(2, 2); CPA_COMMIT();

    for (int c = 0; c < nst; c++) {
        CPA_WAIT2();
        __syncthreads();
        if (c + 3 < nst) produce(c + 3, (c + 3) & 3);
        CPA_COMMIT();

        const uint32_t abase = sbase + SM_A + (c & 3) * SM_ASTG;
        const uint32_t bbase = sbase + SM_B + (c & 3) * SM_BSTG;

        uint32_t afrag[4][4];
        #pragma unroll
        for (int mi = 0; mi < 4; mi++)
            ldsm4(afrag[mi], abase + (m0w + mi * 16 + l16) * ASTRB + lhi * 16);

        uint32_t bfrag[8][2];
        #pragma unroll
        for (int np = 0; np < 4; np++) {
            uint32_t r[4];
            ldsm4t(r, bbase + l16 * BSTRB + (n0w + np * 16 + lhi * 8) * 2);
            bfrag[np * 2 + 0][0] = r[0]; bfrag[np * 2 + 0][1] = r[1];
            bfrag[np * 2 + 1][0] = r[2]; bfrag[np * 2 + 1][1] = r[3];
        }

        #pragma unroll
        for (int mi = 0; mi < 4; mi++)
            #pragma unroll
            for (int ni = 0; ni < 8; ni++)
                mma_f16(acc[mi][ni], afrag[mi], bfrag[ni]);
    }

    // ---- epilogue ----
    #pragma unroll
    for (int mi = 0; mi < 4; mi++) {
        int r0 = m0w + mi * 16 + qr;
        int r1 = r0 + 8;
        int e0 = s_entry[r0];
        int e1 = s_entry[r1];
        #pragma unroll
        for (int ni = 0; ni < 8; ni++) {
            int ncol = n0 + n0w + ni * 8 + qc * 2;
            float bx = bv[ncol], by = bv[ncol + 1];
            if (FC1) {
                if (e0 >= 0) {
                    float v0 = acc[mi][ni][0] + bx;
                    float v1 = acc[mi][ni][1] + by;
                    v0 = v0 > 0.f ? v0 : 0.f;
                    v1 = v1 > 0.f ? v1 : 0.f;
                    *(__half2*)(g_Hh + (size_t)e0 * EXPERT_DIM + ncol) =
                        __floats2half2_rn(v0, v1);
                }
                if (e1 >= 0) {
                    float v0 = acc[mi][ni][2] + bx;
                    float v1 = acc[mi][ni][3] + by;
                    v0 = v0 > 0.f ? v0 : 0.f;
                    v1 = v1 > 0.f ? v1 : 0.f;
                    *(__half2*)(g_Hh + (size_t)e1 * EXPERT_DIM + ncol) =
                        __floats2half2_rn(v0, v1);
                }
            } else {
                if (e0 >= 0) {
                    float w = g_rw[e0];
                    float* p = out + (size_t)(e0 >> 1) * D_MODEL + ncol;
                    atomicAdd(p,     w * (acc[mi][ni][0] + bx));
                    atomicAdd(p + 1, w * (acc[mi][ni][1] + by));
                }
                if (e1 >= 0) {
                    float w = g_rw[e1];
                    float* p = out + (size_t)(e1 >> 1) * D_MODEL + ncol;
                    atomicAdd(p,     w * (acc[mi][ni][2] + bx));
                    atomicAdd(p + 1, w * (acc[mi][ni][3] + by));
                }
            }
        }
    }
}

extern "C" void kernel_launch(void* const* d_in, const int* in_sizes, int n_in,
                              void* d_out, int out_size) {
    (void)in_sizes; (void)n_in; (void)out_size;
    const float* x    = (const float*)d_in[0];
    const float* Wg   = (const float*)d_in[1];
    const float* bg   = (const float*)d_in[2];
    const float* bias = (const float*)d_in[3];
    const float* W1   = (const float*)d_in[4];
    const float* b1   = (const float*)d_in[5];
    const float* W2   = (const float*)d_in[6];
    const float* b2   = (const float*)d_in[7];
    float* out = (float*)d_out;

    static int attr_done = 0;
    if (!attr_done) {
        cudaFuncSetAttribute(expert_mma<D_MODEL, EXPERT_DIM, true>,
                             cudaFuncAttributeMaxDynamicSharedMemorySize, SM_TOTAL);
        cudaFuncSetAttribute(expert_mma<EXPERT_DIM, D_MODEL, false>,
                             cudaFuncAttributeMaxDynamicSharedMemorySize, SM_TOTAL);
        attr_done = 1;
    }

    zero_cnt_kernel<<<1, 32>>>();
    zero_out_kernel<<<(NTOK * D_MODEL / 4 + 255) / 256, 256>>>((float4*)out, NTOK * D_MODEL / 4);
    gate_kernel<<<NTOK / 8, 256>>>(x, Wg, bg, bias);

    __half *xh, *w1h, *w2h;
    cudaGetSymbolAddress((void**)&xh,  g_Xh);
    cudaGetSymbolAddress((void**)&w1h, g_W1h);
    cudaGetSymbolAddress((void**)&w2h, g_W2h);
    {
        int n8x = NTOK * D_MODEL / 8;
        int n8w = NUM_EXPERTS * D_MODEL * EXPERT_DIM / 8;
        cvt_h_kernel<<<(n8x + 255) / 256, 256>>>(x,  xh,  n8x);
        cvt_h_kernel<<<(n8w + 255) / 256, 256>>>(W1, w1h, n8w);
        cvt_h_kernel<<<(n8w + 255) / 256, 256>>>(W2, w2h, n8w);
    }

    expert_mma<D_MODEL, EXPERT_DIM, true >
        <<<dim3(EXPERT_DIM / 256, NTOK / 128, NUM_EXPERTS), 256, SM_TOTAL>>>(w1h, b1, out);
    expert_mma<EXPERT_DIM, D_MODEL, false>
        <<<dim3(D_MODEL / 256,  NTOK / 128, NUM_EXPERTS), 256, SM_TOTAL>>>(w2h, b2, out);
}

// round 8
// speedup vs baseline: 1.9339x; 1.0264x over previous
#include <cuda_runtime.h>
#include <cuda_fp16.h>
#include <stdint.h>
#include <math.h>

#define D_MODEL     1024
#define EXPERT_DIM  2048
#define NUM_EXPERTS 16
#define SEQ_LEN     2048
#define BATCH       2
#define NTOK        (SEQ_LEN*BATCH)      // 4096 tokens
#define NASSIGN     (NTOK*2)             // 8192 (token, k) assignments

// ---- scratch (static __device__: no allocations allowed) ----
__device__ __half g_Xh[(size_t)NTOK * D_MODEL];                        // 8 MB
__device__ __half g_Hh[(size_t)NASSIGN * EXPERT_DIM];                  // 32 MB
__device__ __half g_W1h[(size_t)NUM_EXPERTS * D_MODEL * EXPERT_DIM];   // 64 MB
__device__ __half g_W2h[(size_t)NUM_EXPERTS * EXPERT_DIM * D_MODEL];   // 64 MB
__device__ int   g_cnt[NUM_EXPERTS];
__device__ int   g_list[NUM_EXPERTS * NTOK];
__device__ float g_rw[NASSIGN];

__global__ void zero_cnt_kernel() {
    if (threadIdx.x < NUM_EXPERTS) g_cnt[threadIdx.x] = 0;
}

__global__ void zero_out_kernel(float4* __restrict__ out, int n4) {
    int i = blockIdx.x * blockDim.x + threadIdx.x;
    if (i < n4) out[i] = make_float4(0.f, 0.f, 0.f, 0.f);
}

// ---- fp32 -> fp16 (RN), 8 elems/thread ----
__global__ void cvt_h_kernel(const float* __restrict__ in, __half* __restrict__ out, int n8) {
    int i = blockIdx.x * blockDim.x + threadIdx.x;
    if (i >= n8) return;
    const float4* in4 = (const float4*)in;
    float4 a = in4[2 * i], b = in4[2 * i + 1];
    __half2 h[4];
    h[0] = __floats2half2_rn(a.x, a.y);
    h[1] = __floats2half2_rn(a.z, a.w);
    h[2] = __floats2half2_rn(b.x, b.y);
    h[3] = __floats2half2_rn(b.z, b.w);
    *(uint4*)(out + 8 * (size_t)i) = *(uint4*)h;
}

// ---- gating: one warp per token (fp32, raw x) ----
__global__ void gate_kernel(const float* __restrict__ x,
                            const float* __restrict__ Wg,
                            const float* __restrict__ bg,
                            const float* __restrict__ bias) {
    int gwarp = (blockIdx.x * blockDim.x + threadIdx.x) >> 5;
    int lane  = threadIdx.x & 31;
    if (gwarp >= NTOK) return;
    const float* xr = x + (size_t)gwarp * D_MODEL;

    float xv[32];
    #pragma unroll
    for (int j = 0; j < 32; j++) xv[j] = xr[lane + 32 * j];

    float logits[NUM_EXPERTS];
    #pragma unroll
    for (int e = 0; e < NUM_EXPERTS; e++) {
        float s = 0.f;
        #pragma unroll
        for (int j = 0; j < 32; j++)
            s += xv[j] * Wg[(size_t)(lane + 32 * j) * NUM_EXPERTS + e];
        #pragma unroll
        for (int o = 16; o; o >>= 1) s += __shfl_xor_sync(0xffffffffu, s, o);
        logits[e] = s + bg[e] + bias[e];
    }

    if (lane == 0) {
        int e0 = 0; float v0 = logits[0];
        #pragma unroll
        for (int e = 1; e < NUM_EXPERTS; e++)
            if (logits[e] > v0) { v0 = logits[e]; e0 = e; }
        int e1 = -1; float v1 = -1e30f;
        #pragma unroll
        for (int e = 0; e < NUM_EXPERTS; e++)
            if (e != e0 && logits[e] > v1) { v1 = logits[e]; e1 = e; }

        float ew1 = __expf(v1 - v0);
        float inv = 1.f / (1.f + ew1);
        g_rw[gwarp * 2 + 0] = inv;
        g_rw[gwarp * 2 + 1] = ew1 * inv;
        int p0 = atomicAdd(&g_cnt[e0], 1);
        g_list[e0 * NTOK + p0] = gwarp * 2 + 0;
        int p1 = atomicAdd(&g_cnt[e1], 1);
        g_list[e1 * NTOK + p1] = gwarp * 2 + 1;
    }
}

// ================= mma / ldmatrix / cp.async helpers =================
__device__ __forceinline__ void mma_f16(float* d, const uint32_t* a, const uint32_t* b) {
    asm volatile(
        "mma.sync.aligned.m16n8k16.row.col.f32.f16.f16.f32 "
        "{%0,%1,%2,%3}, {%4,%5,%6,%7}, {%8,%9}, {%0,%1,%2,%3};\n"
        : "+f"(d[0]), "+f"(d[1]), "+f"(d[2]), "+f"(d[3])
        : "r"(a[0]), "r"(a[1]), "r"(a[2]), "r"(a[3]), "r"(b[0]), "r"(b[1]));
}
__device__ __forceinline__ void ldsm4(uint32_t* r, uint32_t a) {
    asm volatile("ldmatrix.sync.aligned.m8n8.x4.shared.b16 {%0,%1,%2,%3}, [%4];"
        : "=r"(r[0]), "=r"(r[1]), "=r"(r[2]), "=r"(r[3]) : "r"(a));
}
__device__ __forceinline__ void ldsm4t(uint32_t* r, uint32_t a) {
    asm volatile("ldmatrix.sync.aligned.m8n8.x4.trans.shared.b16 {%0,%1,%2,%3}, [%4];"
        : "=r"(r[0]), "=r"(r[1]), "=r"(r[2]), "=r"(r[3]) : "r"(a));
}
__device__ __forceinline__ void cpa16(uint32_t dst, const void* src) {
    asm volatile("cp.async.cg.shared.global [%0], [%1], 16;" :: "r"(dst), "l"(src));
}
#define CPA_COMMIT() asm volatile("cp.async.commit_group;" ::: "memory")
#define CPA_WAIT(n)  asm volatile("cp.async.wait_group %0;" :: "n"(n) : "memory")

// smem layout (5-stage ring, k16/stage, block tile 128m x 256n, fp16):
//   s_entry[128]           @ 0
//   A stages: 5 x 6144 B   @ 512    (A[m][k]: 128 rows x 16 half, stride 48 B)
//   B stages: 5 x 8448 B   @ 31232  (B[k][n]: 16 rows x 256 half, stride 528 B)
#define ASTRB     48
#define BSTRB     528
#define STG       5
#define SM_A      512
#define SM_ASTG   (128 * ASTRB)              // 6144
#define SM_B      (SM_A + STG * SM_ASTG)     // 31232
#define SM_BSTG   (16 * BSTRB)               // 8448
#define SM_TOTAL  (SM_B + STG * SM_BSTG)     // 73472

template<int K, int N, bool FC1>
__global__ __launch_bounds__(256, 1)
void expert_mma(const __half* __restrict__ Wbase,
                const float* __restrict__ BiasBase,
                float* __restrict__ out) {
    extern __shared__ char smem[];
    const int e   = blockIdx.z;
    const int cnt = g_cnt[e];
    const int m0  = blockIdx.y * 128;
    if (m0 >= cnt) return;
    const int n0  = blockIdx.x * 256;

    const __half* W  = Wbase    + (size_t)e * K * N;
    const float*  bv = BiasBase + (size_t)e * N;

    int* s_entry = (int*)smem;
    const uint32_t sbase = (uint32_t)__cvta_generic_to_shared(smem);

    const int tid = threadIdx.x;
    if (tid < 128) {
        int idx = m0 + tid;
        s_entry[tid] = (idx < cnt) ? g_list[e * NTOK + idx] : -1;
    }
    __syncthreads();

    // ---- producer mappings ----
    const int arow_i = tid >> 1;
    const __half* a_src;
    {
        int en = s_entry[arow_i];
        const __half* base = FC1 ? g_Xh : g_Hh;
        size_t stride      = FC1 ? D_MODEL : EXPERT_DIM;
        size_t row         = (en >= 0) ? (size_t)(FC1 ? (en >> 1) : en) : 0;
        a_src = base + row * stride + (tid & 1) * 8;
    }
    const uint32_t a_dst0 = sbase + SM_A + arow_i * ASTRB + (tid & 1) * 16;
    const int bkr = tid >> 4;
    const __half* b_src = W + (size_t)bkr * N + n0 + (tid & 15) * 16;
    const uint32_t b_dst0 = sbase + SM_B + bkr * BSTRB + (tid & 15) * 32;

    auto produce = [&](int c) {
        int s  = c % STG;
        int k0 = c * 16;
        cpa16(a_dst0 + s * SM_ASTG, a_src + k0);
        const __half* bs = b_src + (size_t)k0 * N;
        uint32_t bo = b_dst0 + s * SM_BSTG;
        cpa16(bo,      bs);
        cpa16(bo + 16, bs + 8);
    };

    // ---- consumer mappings: 8 warps = 2m x 4n, warp tile 64x64 ----
    const int lane = tid & 31;
    const int wid  = tid >> 5;
    const int m0w  = (wid & 1) * 64;
    const int n0w  = (wid >> 1) * 64;
    const int qr   = lane >> 2;
    const int qc   = lane & 3;
    const int l16  = lane & 15;
    const int lhi  = lane >> 4;

    float acc[4][8][4];
    #pragma unroll
    for (int mi = 0; mi < 4; mi++)
        #pragma unroll
        for (int ni = 0; ni < 8; ni++)
            #pragma unroll
            for (int j = 0; j < 4; j++) acc[mi][ni][j] = 0.f;

    uint32_t af[2][4][4];
    uint32_t bf[2][8][2];

    auto load_frags = [&](int c, int b) {
        int s = c % STG;
        const uint32_t abase = sbase + SM_A + s * SM_ASTG;
        const uint32_t bbase = sbase + SM_B + s * SM_BSTG;
        #pragma unroll
        for (int mi = 0; mi < 4; mi++)
            ldsm4(af[b][mi], abase + (m0w + mi * 16 + l16) * ASTRB + lhi * 16);
        #pragma unroll
        for (int np = 0; np < 4; np++) {
            uint32_t r[4];
            ldsm4t(r, bbase + l16 * BSTRB + (n0w + np * 16 + lhi * 8) * 2);
            bf[b][np * 2 + 0][0] = r[0]; bf[b][np * 2 + 0][1] = r[1];
            bf[b][np * 2 + 1][0] = r[2]; bf[b][np * 2 + 1][1] = r[3];
        }
    };

    const int nst = K / 16;

    // prologue: fill 4 of 5 stages
    produce(0); CPA_COMMIT();
    produce(1); CPA_COMMIT();
    produce(2); CPA_COMMIT();
    produce(3); CPA_COMMIT();
    CPA_WAIT(3);            // stage 0 landed
    __syncthreads();
    load_frags(0, 0);

    for (int c = 0; c < nst; c++) {
        const int cur = c & 1;
        if (c + 1 < nst) {
            CPA_WAIT(2);    // stage c+1 landed (c+2, c+3 may be in flight)
            __syncthreads();
            if (c + 4 < nst) produce(c + 4);
            CPA_COMMIT();   // uniform group counting
            load_frags(c + 1, cur ^ 1);   // LDSM latency hides behind MMAs below
        }
        #pragma unroll
        for (int mi = 0; mi < 4; mi++)
            #pragma unroll
            for (int ni = 0; ni < 8; ni++)
                mma_f16(acc[mi][ni], af[cur][mi], bf[cur][ni]);
    }

    // ---- epilogue ----
    #pragma unroll
    for (int mi = 0; mi < 4; mi++) {
        int r0 = m0w + mi * 16 + qr;
        int r1 = r0 + 8;
        int e0 = s_entry[r0];
        int e1 = s_entry[r1];
        #pragma unroll
        for (int ni = 0; ni < 8; ni++) {
            int ncol = n0 + n0w + ni * 8 + qc * 2;
            float bx = bv[ncol], by = bv[ncol + 1];
            if (FC1) {
                if (e0 >= 0) {
                    float v0 = acc[mi][ni][0] + bx;
                    float v1 = acc[mi][ni][1] + by;
                    v0 = v0 > 0.f ? v0 : 0.f;
                    v1 = v1 > 0.f ? v1 : 0.f;
                    *(__half2*)(g_Hh + (size_t)e0 * EXPERT_DIM + ncol) =
                        __floats2half2_rn(v0, v1);
                }
                if (e1 >= 0) {
                    float v0 = acc[mi][ni][2] + bx;
                    float v1 = acc[mi][ni][3] + by;
                    v0 = v0 > 0.f ? v0 : 0.f;
                    v1 = v1 > 0.f ? v1 : 0.f;
                    *(__half2*)(g_Hh + (size_t)e1 * EXPERT_DIM + ncol) =
                        __floats2half2_rn(v0, v1);
                }
            } else {
                if (e0 >= 0) {
                    float w = g_rw[e0];
                    float* p = out + (size_t)(e0 >> 1) * D_MODEL + ncol;
                    atomicAdd(p,     w * (acc[mi][ni][0] + bx));
                    atomicAdd(p + 1, w * (acc[mi][ni][1] + by));
                }
                if (e1 >= 0) {
                    float w = g_rw[e1];
                    float* p = out + (size_t)(e1 >> 1) * D_MODEL + ncol;
                    atomicAdd(p,     w * (acc[mi][ni][2] + bx));
                    atomicAdd(p + 1, w * (acc[mi][ni][3] + by));
                }
            }
        }
    }
}

extern "C" void kernel_launch(void* const* d_in, const int* in_sizes, int n_in,
                              void* d_out, int out_size) {
    (void)in_sizes; (void)n_in; (void)out_size;
    const float* x    = (const float*)d_in[0];
    const float* Wg   = (const float*)d_in[1];
    const float* bg   = (const float*)d_in[2];
    const float* bias = (const float*)d_in[3];
    const float* W1   = (const float*)d_in[4];
    const float* b1   = (const float*)d_in[5];
    const float* W2   = (const float*)d_in[6];
    const float* b2   = (const float*)d_in[7];
    float* out = (float*)d_out;

    static int attr_done = 0;
    if (!attr_done) {
        cudaFuncSetAttribute(expert_mma<D_MODEL, EXPERT_DIM, true>,
                             cudaFuncAttributeMaxDynamicSharedMemorySize, SM_TOTAL);
        cudaFuncSetAttribute(expert_mma<EXPERT_DIM, D_MODEL, false>,
                             cudaFuncAttributeMaxDynamicSharedMemorySize, SM_TOTAL);
        attr_done = 1;
    }

    zero_cnt_kernel<<<1, 32>>>();
    zero_out_kernel<<<(NTOK * D_MODEL / 4 + 255) / 256, 256>>>((float4*)out, NTOK * D_MODEL / 4);
    gate_kernel<<<NTOK / 8, 256>>>(x, Wg, bg, bias);

    __half *xh, *w1h, *w2h;
    cudaGetSymbolAddress((void**)&xh,  g_Xh);
    cudaGetSymbolAddress((void**)&w1h, g_W1h);
    cudaGetSymbolAddress((void**)&w2h, g_W2h);
    {
        int n8x = NTOK * D_MODEL / 8;
        int n8w = NUM_EXPERTS * D_MODEL * EXPERT_DIM / 8;
        cvt_h_kernel<<<(n8x + 255) / 256, 256>>>(x,  xh,  n8x);
        cvt_h_kernel<<<(n8w + 255) / 256, 256>>>(W1, w1h, n8w);
        cvt_h_kernel<<<(n8w + 255) / 256, 256>>>(W2, w2h, n8w);
    }

    expert_mma<D_MODEL, EXPERT_DIM, true >
        <<<dim3(EXPERT_DIM / 256, NTOK / 128, NUM_EXPERTS), 256, SM_TOTAL>>>(w1h, b1, out);
    expert_mma<EXPERT_DIM, D_MODEL, false>
        <<<dim3(D_MODEL / 256,  NTOK / 128, NUM_EXPERTS), 256, SM_TOTAL>>>(w2h, b2, out);
}